// round 11
// baseline (speedup 1.0000x reference)
#include <cuda_runtime.h>
#include <cstdint>

#define BATCH 64
#define NTOK  65536            // 256*256
#define KSEL  16384
#define TOTAL (BATCH * NTOK)
#define CANDCAP 4096           // per-batch candidate capacity (global)
#define WCAP    64             // per-warp candidate capacity (expected ~20.5, +10 sigma)
#define MCAP    64             // boundary-bin member capacity (expected ~3)
#define BPB     32             // sweep blocks per batch (2048 / 64)

// ---- device scratch (device globals; no allocations) ----
__device__ uint2    g_cand[BATCH * CANDCAP];  // (u bits, delta bits)
__device__ uint32_t g_nc[BATCH];     // candidate counts (zero-init; reset by finalize)
__device__ uint32_t g_c2[BATCH];     // counts >= P2     (zero-init; reset by finalize)
__device__ uint32_t g_of[BATCH];     // overflow flags   (zero-init; reset by finalize)
__device__ uint32_t g_tick[BATCH];   // per-batch sweep-done tickets (reset by finalize)
__device__ uint32_t g_eqcnt[BATCH];  // tie counter (fallback only; reset by finalize)
__device__ double   g_acc;           // loss accumulator
__device__ unsigned g_done;          // finalize ticket

#define P1F 0.73f
#define P2F 0.77f

// exclusive suffix sum over 256 threads (sum of v for tid' > tid)
__device__ __forceinline__ uint32_t suffix_excl_256(uint32_t v, uint32_t* wsum8) {
    const int t = threadIdx.x, lane = t & 31, w = t >> 5;
    uint32_t s = v;
    #pragma unroll
    for (int off = 1; off < 32; off <<= 1) {
        uint32_t o = __shfl_down_sync(0xFFFFFFFFu, s, off);
        if (lane + off < 32) s += o;
    }
    if (lane == 0) wsum8[w] = s;
    __syncthreads();
    if (t == 0) {
        uint32_t run = 0;
        #pragma unroll
        for (int i = 7; i >= 0; i--) { uint32_t x = wsum8[i]; wsum8[i] = run; run += x; }
    }
    __syncthreads();
    return wsum8[w] + (s - v);
}

// ============================================================================
// ONE kernel. Phase A (all 2048 blocks): 83 MB sweep with provisional
// selection guess (u >= P2), window tokens stash (u, delta) in g_cand.
// Phase B (last block per batch, via ticket): hist-based correction over
// the ~1300 L2-hot candidates; exact boundary-bin rank select.
// Finalize (last phase-B block, via second ticket): write out + reset.
// ============================================================================
__global__ __launch_bounds__(256) void fused_kernel(const float4* __restrict__ zs4,
                                                    const uint4*  __restrict__ sm4,
                                                    const float4* __restrict__ gn4,
                                                    float* __restrict__ out) {
    __shared__ uint2    wbuf[8 * WCAP];
    __shared__ uint32_t wcnt[8];
    __shared__ double   wpart[8];
    __shared__ uint32_t wc2[8];
    __shared__ uint32_t hcnt[1024];
    __shared__ float    hsum[1024];
    __shared__ uint32_t wsum8[8];
    __shared__ uint32_t sBin, sK, mcnt, sLast;
    __shared__ uint32_t mu[MCAP];
    __shared__ float    md[MCAP];
    __shared__ double   dpart[8];

    const int t    = threadIdx.x;
    const int lane = t & 31;
    const int w    = t >> 5;
    const int b    = blockIdx.x >> 5;               // 32 blocks per batch
    const int blockBase = blockIdx.x * 512;

    if (lane == 0) wcnt[w] = 0u;
    __syncwarp();

    const uint32_t P1 = __float_as_uint(P1F);
    const uint32_t P2 = __float_as_uint(P2F);
    const uint32_t W  = P2 - P1;

    // ---------------- Phase A: sweep ----------------
    const int g0 = blockBase + t;
    const int g1 = blockBase + 256 + t;

    uint4  u0 = sm4[g0],                u1 = sm4[g1];
    float4 za0 = __ldcs(&zs4[2 * g0]),  zb0 = __ldcs(&zs4[2 * g0 + 1]);
    float4 za1 = __ldcs(&zs4[2 * g1]),  zb1 = __ldcs(&zs4[2 * g1 + 1]);
    float4 ga0 = __ldcs(&gn4[2 * g0]),  gb0 = __ldcs(&gn4[2 * g0 + 1]);
    float4 ga1 = __ldcs(&gn4[2 * g1]),  gb1 = __ldcs(&gn4[2 * g1 + 1]);

    float d[8];
    d[0] = (za0.x + ga0.x) - (za0.y + ga0.y);
    d[1] = (za0.z + ga0.z) - (za0.w + ga0.w);
    d[2] = (zb0.x + gb0.x) - (zb0.y + gb0.y);
    d[3] = (zb0.z + gb0.z) - (zb0.w + gb0.w);
    d[4] = (za1.x + ga1.x) - (za1.y + ga1.y);
    d[5] = (za1.z + ga1.z) - (za1.w + ga1.w);
    d[6] = (zb1.x + gb1.x) - (zb1.y + gb1.y);
    d[7] = (zb1.z + gb1.z) - (zb1.w + gb1.w);

    uint32_t uu[8] = {u0.x, u0.y, u0.z, u0.w, u1.x, u1.y, u1.z, u1.w};

    float facc = 0.0f;
    uint32_t cnt2 = 0;
    #pragma unroll
    for (int k = 0; k < 8; k++) {
        const float dd = d[k];
        const uint32_t u = uu[k];
        const float c  = __logf(1.0f + __expf(-fabsf(dd)));
        const float sp = c + fmaxf(dd, 0.0f);
        const float t_un = fminf(sp, 100.0f);
        const float t_se = fminf(sp - dd, 100.0f);
        const bool hi = (u >= P2);
        cnt2 += hi;
        facc += hi ? t_se : t_un;
        if ((u - P1) < W) {                         // rare (~4%): stash correction
            uint32_t idx = atomicAdd(&wcnt[w], 1u);
            if (idx < WCAP) wbuf[w * WCAP + idx] = make_uint2(u, __float_as_uint(t_se - t_un));
        }
    }

    double acc = (double)facc;
    #pragma unroll
    for (int off = 16; off > 0; off >>= 1) {
        acc  += __shfl_down_sync(0xFFFFFFFFu, acc,  off);
        cnt2 += __shfl_down_sync(0xFFFFFFFFu, cnt2, off);
    }
    if (lane == 0) { wpart[w] = acc; wc2[w] = cnt2; }
    __syncwarp();

    // per-warp candidate flush
    uint32_t cw = wcnt[w];
    uint32_t n  = (cw > WCAP) ? WCAP : cw;
    uint32_t gbase = 0;
    if (lane == 0) {
        if (cw > WCAP) g_of[b] = 1u;
        gbase = atomicAdd(&g_nc[b], n);
        if (gbase + n > CANDCAP) g_of[b] = 1u;
    }
    gbase = __shfl_sync(0xFFFFFFFFu, gbase, 0);
    for (uint32_t i = lane; i < n; i += 32)
        if (gbase + i < CANDCAP) g_cand[b * CANDCAP + gbase + i] = wbuf[w * WCAP + i];

    // publish all this block's global writes, then take the per-batch ticket
    __threadfence();
    __syncthreads();
    if (t == 0) {
        double bsum = 0.0; uint32_t tot2 = 0;
        #pragma unroll
        for (int i = 0; i < 8; i++) { bsum += wpart[i]; tot2 += wc2[i]; }
        atomicAdd(&g_acc, bsum);
        atomicAdd(&g_c2[b], tot2);
        __threadfence();
        sLast = (atomicAdd(&g_tick[b], 1u) == BPB - 1) ? 1u : 0u;
    }
    __syncthreads();
    if (!sLast) return;
    __threadfence();                                 // acquire others' writes

    // ---------------- Phase B: per-batch correction (last block of batch b)
    const uint32_t nc  = __ldcg(&g_nc[b]);
    const uint32_t c2v = __ldcg(&g_c2[b]);
    bool miss = (__ldcg(&g_of[b]) != 0u) || (c2v >= KSEL) || (c2v + nc < KSEL) || (nc > CANDCAP);
    const uint2* __restrict__ candg = g_cand + b * CANDCAP;

    double corr = 0.0;

    if (!miss) {
        for (int i = t; i < 1024; i += 256) { hcnt[i] = 0u; hsum[i] = 0.0f; }
        if (t == 0) mcnt = 0u;
        __syncthreads();

        // one pass: per-bin count + delta-sum (bins on key bits [10:20))
        for (uint32_t i = t; i < nc; i += 256) {
            uint2 cv;
            cv.x = __ldcg(&candg[i].x); cv.y = __ldcg(&candg[i].y);
            uint32_t bin = (cv.x - P1) >> 10;        // < 1024
            atomicAdd(&hcnt[bin], 1u);
            atomicAdd(&hsum[bin], __uint_as_float(cv.y));
        }
        __syncthreads();

        // suffix scan -> boundary bin at rank Kcur from the top
        const uint32_t Kcur = (uint32_t)KSEL - c2v;
        const int base = t * 4;
        uint32_t p = hcnt[base] + hcnt[base + 1] + hcnt[base + 2] + hcnt[base + 3];
        uint32_t sfx = suffix_excl_256(p, wsum8);
        #pragma unroll
        for (int j = 3; j >= 0; j--) {
            uint32_t h = hcnt[base + j];
            uint32_t s_incl = sfx + h;
            if (sfx < Kcur && s_incl >= Kcur) { sBin = (uint32_t)(base + j); sK = Kcur - sfx; }
            sfx = s_incl;
        }
        __syncthreads();
        const uint32_t bin = sBin;
        const uint32_t rk  = sK;

        // corr_hi: delta-sums of bins strictly above boundary
        float ch = 0.0f;
        for (int i = t; i < 1024; i += 256)
            if ((uint32_t)i > bin) ch += hsum[i];
        corr += (double)ch;

        // gather boundary-bin members (expected ~3)
        for (uint32_t i = t; i < nc; i += 256) {
            uint2 cv;
            cv.x = __ldcg(&candg[i].x); cv.y = __ldcg(&candg[i].y);
            if (((cv.x - P1) >> 10) == bin) {
                uint32_t idx = atomicAdd(&mcnt, 1u);
                if (idx < MCAP) { mu[idx] = cv.x; md[idx] = __uint_as_float(cv.y); }
            }
        }
        __syncthreads();

        if (mcnt <= MCAP) {
            if (w == 0) {                            // exact rank select in warp 0
                const uint32_t m = mcnt;
                float csum = 0.0f;
                for (uint32_t e = lane; e < m; e += 32) {
                    uint32_t ue = mu[e];
                    uint32_t rank = 0;
                    for (uint32_t j = 0; j < m; j++) {
                        uint32_t uj = mu[j];
                        rank += (uj > ue) || (uj == ue && j < e);
                    }
                    if (rank < rk) csum += md[e];
                }
                corr += (double)csum;                // per-lane; block-reduced below
            }
        } else {
            miss = true;
            corr = 0.0;
        }
        __syncthreads();
    }

    if (miss) {
        // ---- exact fallback (never taken): full radix for T + full re-read
        const uint32_t* __restrict__ full =
            reinterpret_cast<const uint32_t*>(
                reinterpret_cast<const uint32_t*>(sm4)) + (size_t)b * NTOK;
        uint32_t Kcur = KSEL;
        uint32_t prefixVal = 0;
        for (int r = 0; r < 4; r++) {
            const int shift = 24 - 8 * r;
            for (int i = t; i < 256; i += 256) hcnt[i] = 0u;
            __syncthreads();
            for (int i = t; i < NTOK; i += 256) {
                uint32_t u = __ldcg(&full[i]);
                bool match = (r == 0) || ((u >> (shift + 8)) == prefixVal);
                if (match) atomicAdd(&hcnt[(u >> shift) & 255u], 1u);
            }
            __syncthreads();
            uint32_t p = hcnt[t];
            uint32_t sfx = suffix_excl_256(p, wsum8);
            uint32_t s_incl = sfx + p;
            if (sfx < Kcur && s_incl >= Kcur) { sBin = (uint32_t)t; sK = Kcur - sfx; }
            __syncthreads();
            prefixVal = (prefixVal << 8) | sBin;
            Kcur = sK;
            __syncthreads();
        }
        const uint32_t T = prefixVal;
        const uint32_t req = sK;

        corr = 0.0;
        const float4* zsb = zs4 + (size_t)b * (NTOK / 2);
        const float4* gnb = gn4 + (size_t)b * (NTOK / 2);
        for (int i = t; i < NTOK / 2; i += 256) {    // 2 tokens per float4
            float4 z = zsb[i], g = gnb[i];
            float dv[2] = {(z.x + g.x) - (z.y + g.y), (z.z + g.z) - (z.w + g.w)};
            #pragma unroll
            for (int c = 0; c < 2; c++) {
                uint32_t u = __ldcg(&full[2 * i + c]);
                bool assumed = (u >= P2);
                bool truesel;
                if (u > T)       truesel = true;
                else if (u == T) truesel = (atomicAdd(&g_eqcnt[b], 1u) < req);
                else             truesel = false;
                if (truesel != assumed) {
                    float dd = dv[c];
                    float cc = __logf(1.0f + __expf(-fabsf(dd)));
                    float sp = cc + fmaxf(dd, 0.0f);
                    float delta = fminf(sp - dd, 100.0f) - fminf(sp, 100.0f);
                    corr += truesel ? (double)delta : -(double)delta;
                }
            }
        }
    }

    // ---- block reduce corr, add, finalize via ticket over BATCH blocks ----
    #pragma unroll
    for (int off = 16; off > 0; off >>= 1)
        corr += __shfl_down_sync(0xFFFFFFFFu, corr, off);
    if (lane == 0) dpart[w] = corr;
    __syncthreads();

    if (t == 0) {
        double bsum = 0.0;
        #pragma unroll
        for (int i = 0; i < 8; i++) bsum += dpart[i];
        atomicAdd(&g_acc, bsum);
        __threadfence();
        unsigned ticket = atomicAdd(&g_done, 1u);
        if (ticket == BATCH - 1) {                   // last phase-B block
            __threadfence();
            out[0] = (float)atomicAdd(&g_acc, 0.0);
            #pragma unroll 4
            for (int i = 0; i < BATCH; i++) {
                g_c2[i] = 0u; g_nc[i] = 0u; g_of[i] = 0u;
                g_eqcnt[i] = 0u; g_tick[i] = 0u;
            }
            g_acc = 0.0;
            __threadfence();
            g_done = 0u;
        }
    }
}

extern "C" void kernel_launch(void* const* d_in, const int* in_sizes, int n_in,
                              void* d_out, int out_size) {
    const float* scores = (const float*)d_in[0];   // [B, N, 2]
    const float* smap   = (const float*)d_in[1];   // [B, 1, H, W] == [B, N]
    const float* gumb   = (const float*)d_in[2];   // [B, N, 2]
    float* out = (float*)d_out;

    fused_kernel<<<2048, 256>>>((const float4*)scores, (const uint4*)smap,
                                (const float4*)gumb, out);
}

// round 12
// speedup vs baseline: 1.0683x; 1.0683x over previous
#include <cuda_runtime.h>
#include <cstdint>

#define BATCH 64
#define NTOK  65536            // 256*256
#define KSEL  16384
#define TOTAL (BATCH * NTOK)
#define CANDCAP 4096           // per-batch candidate capacity (global)
#define WCAP    64             // per-warp candidate capacity (expected ~20.5, +10 sigma)
#define MCAP    64             // boundary-bin member capacity (expected ~3)

// ---- device scratch (device globals; no allocations) ----
__device__ uint2    g_cand[BATCH * CANDCAP];  // (u bits, delta bits)
__device__ uint32_t g_nc[BATCH];     // candidate counts (zero-init; reset by finalize)
__device__ uint32_t g_c2[BATCH];     // counts >= P2     (zero-init; reset by finalize)
__device__ uint32_t g_of[BATCH];     // overflow flags   (zero-init; reset by finalize)
__device__ uint32_t g_eqcnt[BATCH];  // tie counter (fallback only; reset by finalize)
__device__ double   g_acc;           // loss accumulator
__device__ unsigned g_done;          // finalize ticket

#define P1F 0.73f
#define P2F 0.77f

// ============================================================================
// Kernel 1: THE sweep (83 MB). Identical to R10 (best measured).
// Provisional sel guess: u >= P2 (certain outside window [P1,P2)); window
// tokens stash (u, delta) where delta = min(sp-d,100) - min(sp,100).
// ============================================================================
__global__ __launch_bounds__(256) void sweep_kernel(const float4* __restrict__ zs4,
                                                    const uint4*  __restrict__ sm4,
                                                    const float4* __restrict__ gn4) {
    __shared__ uint2    wbuf[8 * WCAP];
    __shared__ uint32_t wcnt[8];
    __shared__ double   wpart[8];
    __shared__ uint32_t wc2[8];

    const int t    = threadIdx.x;
    const int lane = t & 31;
    const int w    = t >> 5;
    const int b    = blockIdx.x >> 5;               // 32 blocks per batch
    const int blockBase = blockIdx.x * 512;

    if (lane == 0) wcnt[w] = 0u;
    __syncwarp();

    const uint32_t P1 = __float_as_uint(P1F);
    const uint32_t P2 = __float_as_uint(P2F);
    const uint32_t W  = P2 - P1;

    const int g0 = blockBase + t;
    const int g1 = blockBase + 256 + t;

    uint4  u0 = sm4[g0],                u1 = sm4[g1];
    float4 za0 = __ldcs(&zs4[2 * g0]),  zb0 = __ldcs(&zs4[2 * g0 + 1]);
    float4 za1 = __ldcs(&zs4[2 * g1]),  zb1 = __ldcs(&zs4[2 * g1 + 1]);
    float4 ga0 = __ldcs(&gn4[2 * g0]),  gb0 = __ldcs(&gn4[2 * g0 + 1]);
    float4 ga1 = __ldcs(&gn4[2 * g1]),  gb1 = __ldcs(&gn4[2 * g1 + 1]);

    float d[8];
    d[0] = (za0.x + ga0.x) - (za0.y + ga0.y);
    d[1] = (za0.z + ga0.z) - (za0.w + ga0.w);
    d[2] = (zb0.x + gb0.x) - (zb0.y + gb0.y);
    d[3] = (zb0.z + gb0.z) - (zb0.w + gb0.w);
    d[4] = (za1.x + ga1.x) - (za1.y + ga1.y);
    d[5] = (za1.z + ga1.z) - (za1.w + ga1.w);
    d[6] = (zb1.x + gb1.x) - (zb1.y + gb1.y);
    d[7] = (zb1.z + gb1.z) - (zb1.w + gb1.w);

    uint32_t uu[8] = {u0.x, u0.y, u0.z, u0.w, u1.x, u1.y, u1.z, u1.w};

    float facc = 0.0f;
    uint32_t cnt2 = 0;
    #pragma unroll
    for (int k = 0; k < 8; k++) {
        const float dd = d[k];
        const uint32_t u = uu[k];
        const float c  = __logf(1.0f + __expf(-fabsf(dd)));
        const float sp = c + fmaxf(dd, 0.0f);
        const float t_un = fminf(sp, 100.0f);
        const float t_se = fminf(sp - dd, 100.0f);
        const bool hi = (u >= P2);
        cnt2 += hi;
        facc += hi ? t_se : t_un;
        if ((u - P1) < W) {                         // rare (~4%): stash correction
            uint32_t idx = atomicAdd(&wcnt[w], 1u);
            if (idx < WCAP) wbuf[w * WCAP + idx] = make_uint2(u, __float_as_uint(t_se - t_un));
        }
    }

    double acc = (double)facc;
    #pragma unroll
    for (int off = 16; off > 0; off >>= 1) {
        acc  += __shfl_down_sync(0xFFFFFFFFu, acc,  off);
        cnt2 += __shfl_down_sync(0xFFFFFFFFu, cnt2, off);
    }
    if (lane == 0) { wpart[w] = acc; wc2[w] = cnt2; }
    __syncwarp();

    uint32_t cw = wcnt[w];
    uint32_t n  = (cw > WCAP) ? WCAP : cw;
    uint32_t gbase = 0;
    if (lane == 0) {
        if (cw > WCAP) g_of[b] = 1u;
        gbase = atomicAdd(&g_nc[b], n);
        if (gbase + n > CANDCAP) g_of[b] = 1u;
    }
    gbase = __shfl_sync(0xFFFFFFFFu, gbase, 0);
    for (uint32_t i = lane; i < n; i += 32)
        if (gbase + i < CANDCAP) g_cand[b * CANDCAP + gbase + i] = wbuf[w * WCAP + i];

    __syncthreads();
    if (t == 0) {
        double bsum = 0.0; uint32_t tot2 = 0;
        #pragma unroll
        for (int i = 0; i < 8; i++) { bsum += wpart[i]; tot2 += wc2[i]; }
        atomicAdd(&g_acc, bsum);
        atomicAdd(&g_c2[b], tot2);
    }
}

// ============================================================================
// Kernel 2: per-batch correction, ONE global-read round.
// 64 blocks x 1024 threads: each thread register-loads <=2 candidates,
// histograms (count + delta-sum) on 1024 bins, suffix-scans 1 bin/thread,
// resolves the boundary bin from the same registers.
// Miss fallback (never taken): full radix + full re-read. Finalize via ticket.
// ============================================================================
__device__ __forceinline__ uint32_t suffix_excl_1024(uint32_t v, uint32_t* wsum) {
    const int t = threadIdx.x, lane = t & 31, w = t >> 5;
    uint32_t s = v;
    #pragma unroll
    for (int off = 1; off < 32; off <<= 1) {
        uint32_t o = __shfl_down_sync(0xFFFFFFFFu, s, off);
        if (lane + off < 32) s += o;
    }
    if (lane == 0) wsum[w] = s;
    __syncthreads();
    if (t < 32) {
        uint32_t x  = wsum[t];
        uint32_t sx = x;
        #pragma unroll
        for (int off = 1; off < 32; off <<= 1) {
            uint32_t o = __shfl_down_sync(0xFFFFFFFFu, sx, off);
            if (lane + off < 32) sx += o;
        }
        wsum[t] = sx - x;                 // exclusive suffix of warp sums
    }
    __syncthreads();
    return wsum[w] + (s - v);
}

__global__ __launch_bounds__(1024) void fix_kernel(const float4* __restrict__ zs4,
                                                   const float*  __restrict__ smap,
                                                   const float4* __restrict__ gn4,
                                                   float* __restrict__ out) {
    __shared__ uint32_t hcnt[1024];
    __shared__ float    hsum[1024];
    __shared__ uint32_t wsum[32];
    __shared__ uint32_t sBin, sK, mcnt;
    __shared__ uint32_t mu[MCAP];
    __shared__ float    md[MCAP];
    __shared__ double   dpart[32];

    const int b = blockIdx.x;
    const int t = threadIdx.x;
    const int lane = t & 31;
    const int w    = t >> 5;
    const uint32_t P1 = __float_as_uint(P1F);
    const uint32_t P2 = __float_as_uint(P2F);

    const uint32_t nc  = g_nc[b];
    const uint32_t c2v = g_c2[b];
    bool miss = (g_of[b] != 0u) || (c2v >= KSEL) || (c2v + nc < KSEL) || (nc > CANDCAP);

    const uint2* __restrict__ candg = g_cand + b * CANDCAP;
    const uint32_t* __restrict__ full =
        reinterpret_cast<const uint32_t*>(smap) + (size_t)b * NTOK;

    double corr = 0.0;

    if (!miss) {
        // ---- ONE global-read round: <=4 candidates into registers ----
        uint2 cv[4];
        bool  valid[4];
        #pragma unroll
        for (int j = 0; j < 4; j++) {
            uint32_t i = (uint32_t)t + (uint32_t)j * 1024u;
            valid[j] = (i < nc);
            if (valid[j]) cv[j] = __ldcg(&candg[i]);
        }
        hcnt[t] = 0u; hsum[t] = 0.0f;
        if (t == 0) mcnt = 0u;
        __syncthreads();

        // histogram: per-bin count + delta-sum (bins = key bits [10:20))
        #pragma unroll
        for (int j = 0; j < 4; j++) {
            if (valid[j]) {
                uint32_t bin = (cv[j].x - P1) >> 10;      // < 1024
                atomicAdd(&hcnt[bin], 1u);
                atomicAdd(&hsum[bin], __uint_as_float(cv[j].y));
            }
        }
        __syncthreads();

        // suffix scan, 1 bin/thread -> boundary bin at rank Kcur from top
        const uint32_t Kcur = (uint32_t)KSEL - c2v;
        uint32_t p   = hcnt[t];
        uint32_t sfx = suffix_excl_1024(p, wsum);
        uint32_t s_incl = sfx + p;
        if (sfx < Kcur && s_incl >= Kcur) { sBin = (uint32_t)t; sK = Kcur - sfx; }
        __syncthreads();
        const uint32_t bin = sBin;
        const uint32_t rk  = sK;

        // corr_hi: delta-sums of bins strictly above boundary (1 bin/thread)
        if ((uint32_t)t > bin) corr += (double)hsum[t];

        // boundary members straight from registers (expected ~3 total)
        #pragma unroll
        for (int j = 0; j < 4; j++) {
            if (valid[j] && ((cv[j].x - P1) >> 10) == bin) {
                uint32_t idx = atomicAdd(&mcnt, 1u);
                if (idx < MCAP) { mu[idx] = cv[j].x; md[idx] = __uint_as_float(cv[j].y); }
            }
        }
        __syncthreads();

        if (mcnt <= MCAP) {
            if (w == 0) {                 // exact rank select in warp 0
                const uint32_t m = mcnt;
                float csum = 0.0f;
                for (uint32_t e = lane; e < m; e += 32) {
                    uint32_t ue = mu[e];
                    uint32_t rank = 0;
                    for (uint32_t j = 0; j < m; j++) {
                        uint32_t uj = mu[j];
                        rank += (uj > ue) || (uj == ue && j < e);
                    }
                    if (rank < rk) csum += md[e];
                }
                corr += (double)csum;     // per-lane; block-reduced below
            }
        } else {
            miss = true;
            corr = 0.0;
        }
        __syncthreads();
    }

    if (miss) {
        // ---- exact fallback (never taken): full radix for T + full re-read
        uint32_t Kcur = KSEL;
        uint32_t prefixVal = 0;
        for (int r = 0; r < 4; r++) {
            const int shift = 24 - 8 * r;
            if (t < 256) hcnt[t] = 0u;
            __syncthreads();
            for (int i = t; i < NTOK; i += 1024) {
                uint32_t u = full[i];
                bool match = (r == 0) || ((u >> (shift + 8)) == prefixVal);
                if (match) atomicAdd(&hcnt[(u >> shift) & 255u], 1u);
            }
            __syncthreads();
            uint32_t p = (t < 256) ? hcnt[t] : 0u;
            uint32_t sfx = suffix_excl_1024(p, wsum);
            if (t < 256) {
                uint32_t s_incl = sfx + p;
                if (sfx < Kcur && s_incl >= Kcur) { sBin = (uint32_t)t; sK = Kcur - sfx; }
            }
            __syncthreads();
            prefixVal = (prefixVal << 8) | sBin;
            Kcur = sK;
            __syncthreads();
        }
        const uint32_t T = prefixVal;
        const uint32_t req = sK;

        corr = 0.0;
        const float4* zsb = zs4 + (size_t)b * (NTOK / 2);
        const float4* gnb = gn4 + (size_t)b * (NTOK / 2);
        for (int i = t; i < NTOK / 2; i += 1024) {     // 2 tokens per float4
            float4 z = zsb[i], g = gnb[i];
            float dv[2] = {(z.x + g.x) - (z.y + g.y), (z.z + g.z) - (z.w + g.w)};
            #pragma unroll
            for (int c = 0; c < 2; c++) {
                uint32_t u = full[2 * i + c];
                bool assumed = (u >= P2);
                bool truesel;
                if (u > T)       truesel = true;
                else if (u == T) truesel = (atomicAdd(&g_eqcnt[b], 1u) < req);
                else             truesel = false;
                if (truesel != assumed) {
                    float dd = dv[c];
                    float cc = __logf(1.0f + __expf(-fabsf(dd)));
                    float sp = cc + fmaxf(dd, 0.0f);
                    float delta = fminf(sp - dd, 100.0f) - fminf(sp, 100.0f);
                    corr += truesel ? (double)delta : -(double)delta;
                }
            }
        }
    }

    // ---- block reduce corr, add, finalize via ticket over BATCH blocks ----
    #pragma unroll
    for (int off = 16; off > 0; off >>= 1)
        corr += __shfl_down_sync(0xFFFFFFFFu, corr, off);
    if (lane == 0) dpart[w] = corr;
    __syncthreads();

    if (t == 0) {
        double bsum = 0.0;
        #pragma unroll
        for (int i = 0; i < 32; i++) bsum += dpart[i];
        atomicAdd(&g_acc, bsum);
        __threadfence();
        unsigned ticket = atomicAdd(&g_done, 1u);
        if (ticket == BATCH - 1) {                   // last block: finalize + reset
            __threadfence();
            out[0] = (float)atomicAdd(&g_acc, 0.0);
            #pragma unroll 4
            for (int i = 0; i < BATCH; i++) {
                g_c2[i] = 0u; g_nc[i] = 0u; g_of[i] = 0u; g_eqcnt[i] = 0u;
            }
            g_acc = 0.0;
            __threadfence();
            g_done = 0u;
        }
    }
}

extern "C" void kernel_launch(void* const* d_in, const int* in_sizes, int n_in,
                              void* d_out, int out_size) {
    const float* scores = (const float*)d_in[0];   // [B, N, 2]
    const float* smap   = (const float*)d_in[1];   // [B, 1, H, W] == [B, N]
    const float* gumb   = (const float*)d_in[2];   // [B, N, 2]
    float* out = (float*)d_out;

    sweep_kernel<<<2048, 256>>>((const float4*)scores, (const uint4*)smap,
                                (const float4*)gumb);
    fix_kernel<<<BATCH, 1024>>>((const float4*)scores, smap, (const float4*)gumb, out);
}

// round 13
// speedup vs baseline: 1.0724x; 1.0039x over previous
#include <cuda_runtime.h>
#include <cstdint>

#define BATCH 64
#define NTOK  65536            // 256*256
#define KSEL  16384
#define TOTAL (BATCH * NTOK)
#define CANDCAP 4096           // per-batch candidate capacity (global)
#define WCAP    64             // per-warp candidate capacity (expected ~20.5, +10 sigma)
#define MCAP    64             // boundary-bin member capacity (expected ~3)
#define BPB     32             // sweep blocks per batch (2048 / 64)

// ---- device scratch (device globals; no allocations) ----
__device__ uint2    g_cand[BATCH * CANDCAP];  // (u bits, delta bits)
__device__ uint32_t g_nc[BATCH];     // candidate counts (zero-init; reset by finalize)
__device__ uint32_t g_c2[BATCH];     // counts >= P2     (zero-init; reset by finalize)
__device__ uint32_t g_of[BATCH];     // overflow flags   (zero-init; reset by finalize)
__device__ uint32_t g_tick[BATCH];   // per-batch tickets (reset by finalize)
__device__ uint32_t g_eqcnt[BATCH];  // tie counter (fallback only; reset by finalize)
__device__ double   g_acc;           // loss accumulator
__device__ uint32_t g_done;          // finalize ticket

#define P1F 0.73f
#define P2F 0.77f

__device__ __forceinline__ uint32_t atom_add_acq_rel_gpu(uint32_t* p, uint32_t v) {
    uint32_t old;
    asm volatile("atom.acq_rel.gpu.global.add.u32 %0, [%1], %2;"
                 : "=r"(old) : "l"(p), "r"(v) : "memory");
    return old;
}

// exclusive suffix sum over 256 threads (sum of v for tid' > tid)
__device__ __forceinline__ uint32_t suffix_excl_256(uint32_t v, uint32_t* wsum8) {
    const int t = threadIdx.x, lane = t & 31, w = t >> 5;
    uint32_t s = v;
    #pragma unroll
    for (int off = 1; off < 32; off <<= 1) {
        uint32_t o = __shfl_down_sync(0xFFFFFFFFu, s, off);
        if (lane + off < 32) s += o;
    }
    if (lane == 0) wsum8[w] = s;
    __syncthreads();
    if (t == 0) {
        uint32_t run = 0;
        #pragma unroll
        for (int i = 7; i >= 0; i--) { uint32_t x = wsum8[i]; wsum8[i] = run; run += x; }
    }
    __syncthreads();
    return wsum8[w] + (s - v);
}

// ============================================================================
// ONE kernel. Phase A (all 2048 blocks): 83 MB sweep, provisional selection
// guess (u >= P2), window tokens stash (u, delta) in g_cand.
// Per-batch ticket = ONE acq_rel atomic by t0 (the R11 mistake was 524k
// full-thread __threadfence calls). Phase B (last block per batch): hist
// correction over the L2-hot candidates. Finalize via second ticket.
// ============================================================================
__global__ __launch_bounds__(256) void fused_kernel(const float4* __restrict__ zs4,
                                                    const uint4*  __restrict__ sm4,
                                                    const float4* __restrict__ gn4,
                                                    float* __restrict__ out) {
    __shared__ uint2    wbuf[8 * WCAP];
    __shared__ uint32_t wcnt[8];
    __shared__ double   wpart[8];
    __shared__ uint32_t wc2[8];
    __shared__ uint32_t hcnt[1024];
    __shared__ float    hsum[1024];
    __shared__ uint32_t wsum8[8];
    __shared__ uint32_t sBin, sK, mcnt, sLast;
    __shared__ uint32_t mu[MCAP];
    __shared__ float    md[MCAP];
    __shared__ double   dpart[8];

    const int t    = threadIdx.x;
    const int lane = t & 31;
    const int w    = t >> 5;
    const int b    = blockIdx.x >> 5;               // 32 blocks per batch
    const int blockBase = blockIdx.x * 512;

    if (lane == 0) wcnt[w] = 0u;
    __syncwarp();

    const uint32_t P1 = __float_as_uint(P1F);
    const uint32_t P2 = __float_as_uint(P2F);
    const uint32_t W  = P2 - P1;

    // ---------------- Phase A: sweep (R10-identical math) ----------------
    const int g0 = blockBase + t;
    const int g1 = blockBase + 256 + t;

    uint4  u0 = sm4[g0],                u1 = sm4[g1];
    float4 za0 = __ldcs(&zs4[2 * g0]),  zb0 = __ldcs(&zs4[2 * g0 + 1]);
    float4 za1 = __ldcs(&zs4[2 * g1]),  zb1 = __ldcs(&zs4[2 * g1 + 1]);
    float4 ga0 = __ldcs(&gn4[2 * g0]),  gb0 = __ldcs(&gn4[2 * g0 + 1]);
    float4 ga1 = __ldcs(&gn4[2 * g1]),  gb1 = __ldcs(&gn4[2 * g1 + 1]);

    float d[8];
    d[0] = (za0.x + ga0.x) - (za0.y + ga0.y);
    d[1] = (za0.z + ga0.z) - (za0.w + ga0.w);
    d[2] = (zb0.x + gb0.x) - (zb0.y + gb0.y);
    d[3] = (zb0.z + gb0.z) - (zb0.w + gb0.w);
    d[4] = (za1.x + ga1.x) - (za1.y + ga1.y);
    d[5] = (za1.z + ga1.z) - (za1.w + ga1.w);
    d[6] = (zb1.x + gb1.x) - (zb1.y + gb1.y);
    d[7] = (zb1.z + gb1.z) - (zb1.w + gb1.w);

    uint32_t uu[8] = {u0.x, u0.y, u0.z, u0.w, u1.x, u1.y, u1.z, u1.w};

    float facc = 0.0f;
    uint32_t cnt2 = 0;
    #pragma unroll
    for (int k = 0; k < 8; k++) {
        const float dd = d[k];
        const uint32_t u = uu[k];
        const float c  = __logf(1.0f + __expf(-fabsf(dd)));
        const float sp = c + fmaxf(dd, 0.0f);
        const float t_un = fminf(sp, 100.0f);
        const float t_se = fminf(sp - dd, 100.0f);
        const bool hi = (u >= P2);
        cnt2 += hi;
        facc += hi ? t_se : t_un;
        if ((u - P1) < W) {                         // rare (~4%): stash correction
            uint32_t idx = atomicAdd(&wcnt[w], 1u);
            if (idx < WCAP) wbuf[w * WCAP + idx] = make_uint2(u, __float_as_uint(t_se - t_un));
        }
    }

    double acc = (double)facc;
    #pragma unroll
    for (int off = 16; off > 0; off >>= 1) {
        acc  += __shfl_down_sync(0xFFFFFFFFu, acc,  off);
        cnt2 += __shfl_down_sync(0xFFFFFFFFu, cnt2, off);
    }
    if (lane == 0) { wpart[w] = acc; wc2[w] = cnt2; }
    __syncwarp();

    // per-warp candidate flush
    uint32_t cw = wcnt[w];
    uint32_t n  = (cw > WCAP) ? WCAP : cw;
    uint32_t gbase = 0;
    if (lane == 0) {
        if (cw > WCAP) g_of[b] = 1u;
        gbase = atomicAdd(&g_nc[b], n);
        if (gbase + n > CANDCAP) g_of[b] = 1u;
    }
    gbase = __shfl_sync(0xFFFFFFFFu, gbase, 0);
    for (uint32_t i = lane; i < n; i += 32)
        if (gbase + i < CANDCAP) g_cand[b * CANDCAP + gbase + i] = wbuf[w * WCAP + i];

    __syncthreads();                                // orders all block writes
    if (t == 0) {
        double bsum = 0.0; uint32_t tot2 = 0;
        #pragma unroll
        for (int i = 0; i < 8; i++) { bsum += wpart[i]; tot2 += wc2[i]; }
        atomicAdd(&g_acc, bsum);
        atomicAdd(&g_c2[b], tot2);
        // ONE release atomic publishes this block's work (cheap!)
        sLast = (atom_add_acq_rel_gpu(&g_tick[b], 1u) == BPB - 1) ? 1u : 0u;
    }
    __syncthreads();
    if (!sLast) return;
    // last block of batch b: its t0's acquire + the barrier give visibility

    // ---------------- Phase B: per-batch correction ----------------
    const uint32_t nc  = __ldcg(&g_nc[b]);
    const uint32_t c2v = __ldcg(&g_c2[b]);
    bool miss = (__ldcg(&g_of[b]) != 0u) || (c2v >= KSEL) || (c2v + nc < KSEL) || (nc > CANDCAP);
    const uint2* __restrict__ candg = g_cand + b * CANDCAP;

    double corr = 0.0;

    if (!miss) {
        // register-load my <=6 candidates (nc ~1300, 256 threads)
        uint2 cv[6];
        bool  valid[6];
        #pragma unroll
        for (int j = 0; j < 6; j++) {
            uint32_t i = (uint32_t)t + (uint32_t)j * 256u;
            valid[j] = (i < nc);
            if (valid[j]) cv[j] = __ldcg(&candg[i]);
        }
        for (int i = t; i < 1024; i += 256) { hcnt[i] = 0u; hsum[i] = 0.0f; }
        if (t == 0) mcnt = 0u;
        __syncthreads();

        #pragma unroll
        for (int j = 0; j < 6; j++) {
            if (valid[j]) {
                uint32_t bin = (cv[j].x - P1) >> 10;      // < 1024
                atomicAdd(&hcnt[bin], 1u);
                atomicAdd(&hsum[bin], __uint_as_float(cv[j].y));
            }
        }
        __syncthreads();

        // suffix scan -> boundary bin at rank Kcur from the top
        const uint32_t Kcur = (uint32_t)KSEL - c2v;
        const int base = t * 4;
        uint32_t p = hcnt[base] + hcnt[base + 1] + hcnt[base + 2] + hcnt[base + 3];
        uint32_t sfx = suffix_excl_256(p, wsum8);
        #pragma unroll
        for (int j = 3; j >= 0; j--) {
            uint32_t h = hcnt[base + j];
            uint32_t s_incl = sfx + h;
            if (sfx < Kcur && s_incl >= Kcur) { sBin = (uint32_t)(base + j); sK = Kcur - sfx; }
            sfx = s_incl;
        }
        __syncthreads();
        const uint32_t bin = sBin;
        const uint32_t rk  = sK;

        // corr_hi: delta-sums of bins strictly above boundary
        float ch = 0.0f;
        for (int i = t; i < 1024; i += 256)
            if ((uint32_t)i > bin) ch += hsum[i];
        corr += (double)ch;

        // boundary members from registers (expected ~3)
        #pragma unroll
        for (int j = 0; j < 6; j++) {
            if (valid[j] && ((cv[j].x - P1) >> 10) == bin) {
                uint32_t idx = atomicAdd(&mcnt, 1u);
                if (idx < MCAP) { mu[idx] = cv[j].x; md[idx] = __uint_as_float(cv[j].y); }
            }
        }
        __syncthreads();

        if (mcnt <= MCAP) {
            if (w == 0) {                            // exact rank select in warp 0
                const uint32_t m = mcnt;
                float csum = 0.0f;
                for (uint32_t e = lane; e < m; e += 32) {
                    uint32_t ue = mu[e];
                    uint32_t rank = 0;
                    for (uint32_t j = 0; j < m; j++) {
                        uint32_t uj = mu[j];
                        rank += (uj > ue) || (uj == ue && j < e);
                    }
                    if (rank < rk) csum += md[e];
                }
                corr += (double)csum;                // per-lane; block-reduced below
            }
        } else {
            miss = true;
            corr = 0.0;
        }
        __syncthreads();
    }

    if (miss) {
        // ---- exact fallback (never taken): full radix for T + full re-read
        const uint32_t* __restrict__ full =
            reinterpret_cast<const uint32_t*>(sm4) + (size_t)b * NTOK;
        uint32_t Kcur = KSEL;
        uint32_t prefixVal = 0;
        for (int r = 0; r < 4; r++) {
            const int shift = 24 - 8 * r;
            if (t < 256) hcnt[t] = 0u;
            __syncthreads();
            for (int i = t; i < NTOK; i += 256) {
                uint32_t u = __ldcg(&full[i]);
                bool match = (r == 0) || ((u >> (shift + 8)) == prefixVal);
                if (match) atomicAdd(&hcnt[(u >> shift) & 255u], 1u);
            }
            __syncthreads();
            uint32_t p = hcnt[t];
            uint32_t sfx = suffix_excl_256(p, wsum8);
            uint32_t s_incl = sfx + p;
            if (sfx < Kcur && s_incl >= Kcur) { sBin = (uint32_t)t; sK = Kcur - sfx; }
            __syncthreads();
            prefixVal = (prefixVal << 8) | sBin;
            Kcur = sK;
            __syncthreads();
        }
        const uint32_t T = prefixVal;
        const uint32_t req = sK;

        corr = 0.0;
        const float4* zsb = zs4 + (size_t)b * (NTOK / 2);
        const float4* gnb = gn4 + (size_t)b * (NTOK / 2);
        for (int i = t; i < NTOK / 2; i += 256) {    // 2 tokens per float4
            float4 z = zsb[i], g = gnb[i];
            float dv[2] = {(z.x + g.x) - (z.y + g.y), (z.z + g.z) - (z.w + g.w)};
            #pragma unroll
            for (int c = 0; c < 2; c++) {
                uint32_t u = __ldcg(&full[2 * i + c]);
                bool assumed = (u >= P2);
                bool truesel;
                if (u > T)       truesel = true;
                else if (u == T) truesel = (atomicAdd(&g_eqcnt[b], 1u) < req);
                else             truesel = false;
                if (truesel != assumed) {
                    float dd = dv[c];
                    float cc = __logf(1.0f + __expf(-fabsf(dd)));
                    float sp = cc + fmaxf(dd, 0.0f);
                    float delta = fminf(sp - dd, 100.0f) - fminf(sp, 100.0f);
                    corr += truesel ? (double)delta : -(double)delta;
                }
            }
        }
    }

    // ---- block reduce corr, add, finalize via ticket over BATCH blocks ----
    #pragma unroll
    for (int off = 16; off > 0; off >>= 1)
        corr += __shfl_down_sync(0xFFFFFFFFu, corr, off);
    if (lane == 0) dpart[w] = corr;
    __syncthreads();

    if (t == 0) {
        double bsum = 0.0;
        #pragma unroll
        for (int i = 0; i < 8; i++) bsum += dpart[i];
        atomicAdd(&g_acc, bsum);
        uint32_t ticket = atom_add_acq_rel_gpu(&g_done, 1u);
        if (ticket == BATCH - 1) {                   // last phase-B block
            out[0] = (float)atomicAdd(&g_acc, 0.0);
            #pragma unroll 4
            for (int i = 0; i < BATCH; i++) {
                g_c2[i] = 0u; g_nc[i] = 0u; g_of[i] = 0u;
                g_eqcnt[i] = 0u; g_tick[i] = 0u;
            }
            g_acc = 0.0;
            __threadfence();
            g_done = 0u;
        }
    }
}

extern "C" void kernel_launch(void* const* d_in, const int* in_sizes, int n_in,
                              void* d_out, int out_size) {
    const float* scores = (const float*)d_in[0];   // [B, N, 2]
    const float* smap   = (const float*)d_in[1];   // [B, 1, H, W] == [B, N]
    const float* gumb   = (const float*)d_in[2];   // [B, N, 2]
    float* out = (float*)d_out;

    fused_kernel<<<2048, 256>>>((const float4*)scores, (const uint4*)smap,
                                (const float4*)gumb, out);
}